// round 14
// baseline (speedup 1.0000x reference)
#include <cuda_runtime.h>
#include <cuda_bf16.h>
#include <cstdint>

#define S_LEN 512
#define B_DIM 64
#define I_DIM 512
#define H_DIM 1024
#define EPS_C 1e-10f
#define NB    128

typedef unsigned long long u64;

// ---------------- bf16 helpers ----------------
__device__ __forceinline__ void mma16(float* c, uint32_t a0, uint32_t a1, uint32_t a2, uint32_t a3,
                                      uint32_t b0, uint32_t b1) {
    asm volatile("mma.sync.aligned.m16n8k16.row.col.f32.bf16.bf16.f32 "
        "{%0,%1,%2,%3}, {%4,%5,%6,%7}, {%8,%9}, {%0,%1,%2,%3};"
        : "+f"(c[0]), "+f"(c[1]), "+f"(c[2]), "+f"(c[3])
        : "r"(a0), "r"(a1), "r"(a2), "r"(a3), "r"(b0), "r"(b1));
}
__device__ __forceinline__ uint32_t mulbf2(uint32_t a, uint32_t b) {
    uint32_t d; asm("mul.rn.bf16x2 %0, %1, %2;" : "=r"(d) : "r"(a), "r"(b)); return d;
}
__device__ __forceinline__ uint32_t bpack(float lo, float hi) {
    __nv_bfloat162 t = __floats2bfloat162_rn(lo, hi);   // .x = low half
    return *reinterpret_cast<uint32_t*>(&t);
}
__device__ __forceinline__ float tanh_ap(float x) {
    float y; asm("tanh.approx.f32 %0, %1;" : "=f"(y) : "f"(x)); return y;
}

// bf16 k16-group permutation: original j -> position; order [0,1,8,9,2,3,10,11,...]
__device__ __forceinline__ int kperm16(int j) {
    return (((j & 7) >> 1) << 2) | (((j >> 3) & 1) << 1) | (j & 1);
}

// ---------------- cp.async helpers ----------------
__device__ __forceinline__ uint32_t smem_u32(const void* p) {
    uint32_t a;
    asm("{ .reg .u64 t; cvta.to.shared.u64 t, %1; cvt.u32.u64 %0, t; }" : "=r"(a) : "l"(p));
    return a;
}
__device__ __forceinline__ void cp16(uint32_t dst, const void* src) {
    asm volatile("cp.async.cg.shared.global [%0], [%1], 16;" :: "r"(dst), "l"(src));
}
#define CP_COMMIT() asm volatile("cp.async.commit_group;" ::: "memory")
#define CP_WAIT1()  asm volatile("cp.async.wait_group 1;" ::: "memory")
#define CP_WAIT0()  asm volatile("cp.async.wait_group 0;" ::: "memory")

// ---------------- scoped atomics for the grid barrier ----------------
__device__ __forceinline__ unsigned ld_acquire(const unsigned* p) {
    unsigned v;
    asm volatile("ld.acquire.gpu.u32 %0, [%1];" : "=r"(v) : "l"(p) : "memory");
    return v;
}
__device__ __forceinline__ void st_release(unsigned* p, unsigned v) {
    asm volatile("st.release.gpu.u32 [%0], %1;" :: "l"(p), "r"(v) : "memory");
}

// ---------------- device scratch ----------------
__device__ float g_mu_h[H_DIM * H_DIM];    // fp32, [k][n] (bf16 at scan staging)
__device__ float g_d_h [H_DIM * H_DIM];
// xproj weights pre-merged in smem image: [8 ks][4 cg][4 tg][1024 n-slot] uint4
__device__ __align__(16) uint4 g_wx[8 * 16 * 1024];
__device__ __align__(16) __nv_bfloat16 g_xb16[S_LEN * B_DIM * I_DIM];  // bf16(x), k16-permuted
__device__ __align__(16) __nv_bfloat16 g_xq16[S_LEN * B_DIM * I_DIM];  // bf16(x*x), k16-permuted
__device__ __align__(16) __nv_bfloat16 g_hA[B_DIM * H_DIM];  // bf16 h transport, k16-permuted
__device__ __align__(16) __nv_bfloat16 g_hB[B_DIM * H_DIM];
// per-warp release flags: g_flags[bid*32 + warp], one 128B line per block
__device__ __align__(128) unsigned g_flags[NB * 32];

// ---------------- prep ----------------
__global__ void prep_kernel(const float* __restrict__ m_in, const float* __restrict__ pi_in,
                            const float* __restrict__ chi_in,
                            const float* __restrict__ m_h, const float* __restrict__ pi_h,
                            const float* __restrict__ chi_h)
{
    int idx = blockIdx.x * blockDim.x + threadIdx.x;
    int stride = gridDim.x * blockDim.x;

    for (int i = idx; i < H_DIM * H_DIM; i += stride) {
        float m = m_h[i], pi = pi_h[i], chi = chi_h[i];
        float mu = (1.0f - pi) * m;
        float rho = (1.0f - pi) * (chi + m * m);
        g_mu_h[i] = mu;
        g_d_h[i]  = rho - mu * mu;
    }
    for (int i = idx; i < 8 * 16 * 1024; i += stride) {
        int n  = i & 1023;
        int tg = (i >> 10) & 3;
        int cgks = i >> 12;
        int kA = cgks * 16 + 2 * tg;
        int kB = kA + 8;

        float mv[4], dv[4];
        int kk[4] = {kA, kA + 1, kB, kB + 1};
#pragma unroll
        for (int j = 0; j < 4; j++) {
            int o = kk[j] * H_DIM + n;
            float m = m_in[o], pi = pi_in[o], chi = chi_in[o];
            float mu = (1.0f - pi) * m;
            mv[j] = mu;
            dv[j] = (1.0f - pi) * (chi + m * m) - mu * mu;
        }
        uint4 w;
        w.x = bpack(mv[0], mv[1]);
        w.y = bpack(mv[2], mv[3]);
        w.z = bpack(dv[0], dv[1]);
        w.w = bpack(dv[2], dv[3]);
        int nb = n >> 6, nl = n & 63;
        int slot = nb * 64 + ((nl + 2 * tg) & 63);
        g_wx[(i & ~1023) + slot] = w;
    }
    for (int i = idx; i < (B_DIM * H_DIM) / 2; i += stride)
        reinterpret_cast<uint32_t*>(g_hA)[i] = 0u;
    for (int i = idx; i < NB * 32; i += stride)
        g_flags[i] = 0u;
}

// ---------------- prep_x: bf16(x), bf16(x^2), k16-permuted ----------------
__global__ void prep_x_kernel(const float* __restrict__ x)
{
    int idx = blockIdx.x * blockDim.x + threadIdx.x;
    int stride = gridDim.x * blockDim.x;
    const int N = S_LEN * B_DIM * I_DIM;
    for (int i = idx; i < N; i += stride) {
        int k = i & (I_DIM - 1);
        int m = i >> 9;
        float v = x[i];
        int p = (k & ~15) | kperm16(k & 15);
        int o = (m << 9) | p;
        g_xb16[o] = __float2bfloat16(v);
        g_xq16[o] = __float2bfloat16(v * v);
    }
}

// ---------------- phase B: xproj via bf16 mma.m16n8k16, cp.async pipelined ----------------
#define XP_SMEM (98304)
#define BUF_SZ  49152

__global__ void __launch_bounds__(256, 2) xproj_kernel(const float* __restrict__ eps_in,
                                                       float* __restrict__ out)
{
    extern __shared__ char smx[];
    const uint32_t sb = smem_u32(smx);

    const int tid  = threadIdx.x;
    const int warp = tid >> 5, lane = tid & 31;
    const int gid = lane >> 2, tig = lane & 3;
    const int n_base = blockIdx.x * 64;
    const int m_base = blockIdx.y * 128;
    const int mg = (warp & 3) * 32;
    const int nh = (warp >> 2) * 32;

    auto issue = [&](int ks) {
        const uint32_t boff = sb + (ks & 1) * BUF_SZ;
        for (int i = tid; i < 1024; i += 256) {
            int r = i >> 3, u = i & 7;
            int up = u ^ ((r & 3) << 1);
            const char* src = (const char*)(g_xb16 + (size_t)(m_base + r) * I_DIM + ks * 64) + u * 16;
            const char* srq = (const char*)(g_xq16 + (size_t)(m_base + r) * I_DIM + ks * 64) + u * 16;
            cp16(boff + r * 128 + up * 16, src);
            cp16(boff + 16384 + r * 128 + up * 16, srq);
        }
        for (int i = tid; i < 1024; i += 256) {
            cp16(boff + 32768 + i * 16,
                 (const char*)(g_wx + (((ks * 16 + (i >> 6)) << 10) + n_base + (i & 63))));
        }
    };

    float cG[2][4][4] = {}, cD[2][4][4] = {};

    issue(0); CP_COMMIT();
    issue(1); CP_COMMIT();

    for (int ks = 0; ks < 8; ks++) {
        if (ks < 7) { CP_WAIT1(); } else { CP_WAIT0(); }
        __syncthreads();

        const char* xs = smx + (ks & 1) * BUF_SZ;
        const char* xq = xs + 16384;
        const uint4* w4 = (const uint4*)(xs + 32768);

#pragma unroll
        for (int c = 0; c < 4; c++) {
            uint2 ax[2][2], aq[2][2];
#pragma unroll
            for (int mt = 0; mt < 2; mt++) {
                int r0 = mg + mt * 16 + gid;
                int r1 = r0 + 8;
                int g0 = (c * 4 + tig) ^ ((r0 & 3) << 2);
                int g1 = (c * 4 + tig) ^ ((r1 & 3) << 2);
                ax[mt][0] = *(const uint2*)(xs + r0 * 128 + g0 * 8);
                ax[mt][1] = *(const uint2*)(xs + r1 * 128 + g1 * 8);
                aq[mt][0] = *(const uint2*)(xq + r0 * 128 + g0 * 8);
                aq[mt][1] = *(const uint2*)(xq + r1 * 128 + g1 * 8);
            }
#pragma unroll
            for (int nt = 0; nt < 4; nt++) {
                int nl = nh + nt * 8 + gid;
                uint4 w = w4[(c * 4 + tig) * 64 + ((nl + 2 * tig) & 63)];
#pragma unroll
                for (int mt = 0; mt < 2; mt++) {
                    mma16(cG[mt][nt], ax[mt][0].x, ax[mt][1].x, ax[mt][0].y, ax[mt][1].y, w.x, w.y);
                    mma16(cD[mt][nt], aq[mt][0].x, aq[mt][1].x, aq[mt][0].y, aq[mt][1].y, w.z, w.w);
                }
            }
        }
        __syncthreads();
        if (ks + 2 < 8) { issue(ks + 2); CP_COMMIT(); }
    }

#pragma unroll
    for (int mt = 0; mt < 2; mt++)
#pragma unroll
    for (int nt = 0; nt < 4; nt++) {
        int n = n_base + nh + nt * 8 + tig * 2;
#pragma unroll
        for (int half = 0; half < 2; half++) {
            int m = m_base + mg + mt * 16 + gid + half * 8;
            size_t off = (size_t)m * H_DIM + n;
            float2 e = *(const float2*)(eps_in + off);
            float2 o;
            o.x = cG[mt][nt][half * 2]     + e.x * sqrtf(cD[mt][nt][half * 2]     + EPS_C);
            o.y = cG[mt][nt][half * 2 + 1] + e.y * sqrtf(cD[mt][nt][half * 2 + 1] + EPS_C);
            *(float2*)(out + off) = o;
        }
    }
}

// ---------------- phase C: persistent scan via bf16 mma.m16n8k16 ----------------
// Per-warp producer flags: producer warp w (rows {2w,2w+1}) publishes its own flag
// right after its h stores — no release __syncthreads. Consumer warp (ke,mt) polls
// 64 flags (8 producer blocks x warps [mt*8, mt*8+8)), 2 per lane. psum is
// double-buffered (t&1) so phase-skewed warps can't collide; one __syncthreads
// per step (psum handoff) remains.
#define SC_SMEM (131072)

__global__ void __launch_bounds__(512, 1) scan_kernel(const float* __restrict__ eps_h,
                                                      float* __restrict__ out,
                                                      int write_last)
{
    extern __shared__ char smc[];
    uint4* wpk = (uint4*)smc;                // [64 cg][4 tig][16 n] uint4 = 64KB
    // psum double buffer: buffer b at smc + 65536 + b*32768 (pG 16KB + pD 16KB)

    const int tid  = threadIdx.x;
    const int warp = tid >> 5, lane = tid & 31;
    const int gid = lane >> 2, tig = lane & 3;
    const int n_base = (blockIdx.x >> 1) * 16;
    const int b_base = (blockIdx.x & 1) * 32;
    const int half = blockIdx.x & 1;
    const int mt = warp & 1, ke = warp >> 1;
    const int bid = blockIdx.x;

    // consumer gate flags: producer block (ke*8+p, half), warp w in [mt*8, mt*8+8)
    const int gp = lane >> 2;                          // producer 0..7
    const int gw = mt * 8 + ((lane & 3) << 1);         // first of 2 warps
    unsigned* gf0 = &g_flags[(((ke * 8 + gp) * 2) + half) * 32 + gw];
    unsigned* gf1 = gf0 + 1;

    // stage weights once: mu and d single bf16, packed {mu01, mu89, d01, d89}
    for (int i = tid; i < 4096; i += 512) {
        int cg = i >> 6, tg = (i >> 4) & 3, n = i & 15;
        int sidx = cg * 64 + tg * 16 + ((n + 2 * tg) & 15);
        int k0 = cg * 16 + 2 * tg;
        int gn = n_base + n;
        float m0 = g_mu_h[(size_t)k0 * H_DIM + gn];
        float m1 = g_mu_h[(size_t)(k0 + 1) * H_DIM + gn];
        float m8 = g_mu_h[(size_t)(k0 + 8) * H_DIM + gn];
        float m9 = g_mu_h[(size_t)(k0 + 9) * H_DIM + gn];
        float d0 = g_d_h[(size_t)k0 * H_DIM + gn];
        float d1 = g_d_h[(size_t)(k0 + 1) * H_DIM + gn];
        float d8 = g_d_h[(size_t)(k0 + 8) * H_DIM + gn];
        float d9 = g_d_h[(size_t)(k0 + 9) * H_DIM + gn];
        uint4 w;
        w.x = bpack(m0, m1);
        w.y = bpack(m8, m9);
        w.z = bpack(d0, d1);
        w.w = bpack(d8, d9);
        wpk[sidx] = w;
    }

    const int r0 = b_base + mt * 16 + gid;
    const int eb = tid >> 4;                 // 0..31 (warp w covers eb in {2w, 2w+1})
    const int en = tid & 15;                 // 0..15
    const int gbrow = b_base + eb;
    const int ncol = n_base + en;
    const int hoff = gbrow * H_DIM + (ncol & ~15) + kperm16(ncol & 15);

    // prefetch step-0 epilogue operands
    size_t toff = (size_t)gbrow * H_DIM + ncol;
    float epre = __ldg(eps_h + toff);
    float xpre = __ldcg(out + toff);
    __syncthreads();

    for (int t = 0; t < S_LEN; t++) {
        const __nv_bfloat16* hsrc = (t & 1) ? g_hB : g_hA;
        __nv_bfloat16* hdst = (t & 1) ? g_hA : g_hB;
        float* pG = (float*)(smc + 65536 + (t & 1) * 32768);
        float* pD = pG + 4096;

        // ---- per-warp producer gate (skip t=0: h0 preset by prep) ----
        if (t > 0) {
            const unsigned tgt = (unsigned)t;
            while (ld_acquire(gf0) < tgt) { }
            while (ld_acquire(gf1) < tgt) { }
            __syncwarp();
        }

        // ---- preload all h fragments (16 independent LDG.64, full MLP) ----
        const __nv_bfloat16* hr0 = hsrc + (size_t)r0 * H_DIM + ke * 128 + tig * 4;
        const __nv_bfloat16* hr1 = hr0 + 8 * H_DIM;
        uint2 v0[8], v1[8];
#pragma unroll
        for (int c = 0; c < 8; c++) {
            v0[c] = __ldcg((const uint2*)(hr0 + c * 16));
            v1[c] = __ldcg((const uint2*)(hr1 + c * 16));
        }

        float cG[2][4] = {}, cD[2][4] = {};
#pragma unroll
        for (int c = 0; c < 8; c++) {
            const int cg = ke * 8 + c;
            uint32_t a0 = v0[c].x, a2 = v0[c].y;
            uint32_t a1 = v1[c].x, a3 = v1[c].y;
            uint32_t q0 = mulbf2(a0, a0), q2 = mulbf2(a2, a2);
            uint32_t q1 = mulbf2(a1, a1), q3 = mulbf2(a3, a3);
#pragma unroll
            for (int nt = 0; nt < 2; nt++) {
                int nl = nt * 8 + gid;
                uint4 w = wpk[cg * 64 + tig * 16 + ((nl + 2 * tig) & 15)];
                mma16(cG[nt], a0, a1, a2, a3, w.x, w.y);
                mma16(cD[nt], q0, q1, q2, q3, w.z, w.w);
            }
        }

        // partials -> smem (buffer t&1)
        const int rowa = ke * 32 + mt * 16 + gid;
#pragma unroll
        for (int nt = 0; nt < 2; nt++) {
            int colb = nt * 8 + tig * 2;
            *(float2*)&pG[rowa * 16 + colb]       = make_float2(cG[nt][0], cG[nt][1]);
            *(float2*)&pG[(rowa + 8) * 16 + colb] = make_float2(cG[nt][2], cG[nt][3]);
            *(float2*)&pD[rowa * 16 + colb]       = make_float2(cD[nt][0], cD[nt][1]);
            *(float2*)&pD[(rowa + 8) * 16 + colb] = make_float2(cD[nt][2], cD[nt][3]);
        }
        __syncthreads();                      // the ONLY block sync per step

        // reduce 8 k-slices + epilogue (1 output per thread)
        float G = 0.0f, D = 0.0f;
#pragma unroll
        for (int q = 0; q < 8; q++) {
            G += pG[(q * 32 + eb) * 16 + en];
            D += pD[(q * 32 + eb) * 16 + en];
        }
        float h = tanh_ap(G + epre * sqrtf(D + EPS_C) + xpre);
        hdst[hoff] = __float2bfloat16(h);    // h transport: the only critical store

        if (t == S_LEN - 1) {
            out[toff] = h;
            if (write_last)
                out[(size_t)S_LEN * B_DIM * H_DIM + gbrow * H_DIM + ncol] = h;
            break;
        }

        // ---- per-warp release: this warp's h rows are done ----
        __syncwarp();
        if (lane == 0)
            st_release(&g_flags[bid * 32 + warp], (unsigned)(t + 1));
        // hidden work: current out-store + next-step operand prefetch
        out[toff] = h;
        toff = (size_t)((t + 1) * B_DIM + gbrow) * H_DIM + ncol;
        epre = __ldg(eps_h + toff);
        xpre = __ldcg(out + toff);
    }
}

// ---------------- launch ----------------
extern "C" void kernel_launch(void* const* d_in, const int* in_sizes, int n_in,
                              void* d_out, int out_size)
{
    (void)in_sizes; (void)n_in;
    const float* x      = (const float*)d_in[0];
    const float* eps_in = (const float*)d_in[1];
    const float* eps_h  = (const float*)d_in[2];
    const float* m_in   = (const float*)d_in[3];
    const float* pi_in  = (const float*)d_in[4];
    const float* chi_in = (const float*)d_in[5];
    const float* m_h    = (const float*)d_in[6];
    const float* pi_h   = (const float*)d_in[7];
    const float* chi_h  = (const float*)d_in[8];
    float* out = (float*)d_out;

    prep_kernel<<<1024, 256>>>(m_in, pi_in, chi_in, m_h, pi_h, chi_h);
    prep_x_kernel<<<8192, 256>>>(x);

    cudaFuncSetAttribute(xproj_kernel, cudaFuncAttributeMaxDynamicSharedMemorySize, XP_SMEM);
    dim3 gB(H_DIM / 64, (S_LEN * B_DIM) / 128);
    xproj_kernel<<<gB, 256, XP_SMEM>>>(eps_in, out);

    cudaFuncSetAttribute(scan_kernel, cudaFuncAttributeMaxDynamicSharedMemorySize, SC_SMEM);
    int write_last = (out_size >= S_LEN * B_DIM * H_DIM + B_DIM * H_DIM) ? 1 : 0;
    scan_kernel<<<NB, 512, SC_SMEM>>>(eps_h, out, write_last);
}

// round 15
// speedup vs baseline: 1.7045x; 1.7045x over previous
#include <cuda_runtime.h>
#include <cuda_bf16.h>
#include <cstdint>

#define S_LEN 512
#define B_DIM 64
#define I_DIM 512
#define H_DIM 1024
#define EPS_C 1e-10f
#define NB    128

typedef unsigned long long u64;

// ---------------- bf16 helpers ----------------
__device__ __forceinline__ void mma16(float* c, uint32_t a0, uint32_t a1, uint32_t a2, uint32_t a3,
                                      uint32_t b0, uint32_t b1) {
    asm volatile("mma.sync.aligned.m16n8k16.row.col.f32.bf16.bf16.f32 "
        "{%0,%1,%2,%3}, {%4,%5,%6,%7}, {%8,%9}, {%0,%1,%2,%3};"
        : "+f"(c[0]), "+f"(c[1]), "+f"(c[2]), "+f"(c[3])
        : "r"(a0), "r"(a1), "r"(a2), "r"(a3), "r"(b0), "r"(b1));
}
__device__ __forceinline__ uint32_t mulbf2(uint32_t a, uint32_t b) {
    uint32_t d; asm("mul.rn.bf16x2 %0, %1, %2;" : "=r"(d) : "r"(a), "r"(b)); return d;
}
__device__ __forceinline__ uint32_t bpack(float lo, float hi) {
    __nv_bfloat162 t = __floats2bfloat162_rn(lo, hi);   // .x = low half
    return *reinterpret_cast<uint32_t*>(&t);
}
__device__ __forceinline__ float tanh_ap(float x) {
    float y; asm("tanh.approx.f32 %0, %1;" : "=f"(y) : "f"(x)); return y;
}

// bf16 k16-group permutation: original j -> position; order [0,1,8,9,2,3,10,11,...]
__device__ __forceinline__ int kperm16(int j) {
    return (((j & 7) >> 1) << 2) | (((j >> 3) & 1) << 1) | (j & 1);
}

// ---------------- cp.async helpers ----------------
__device__ __forceinline__ uint32_t smem_u32(const void* p) {
    uint32_t a;
    asm("{ .reg .u64 t; cvta.to.shared.u64 t, %1; cvt.u32.u64 %0, t; }" : "=r"(a) : "l"(p));
    return a;
}
__device__ __forceinline__ void cp16(uint32_t dst, const void* src) {
    asm volatile("cp.async.cg.shared.global [%0], [%1], 16;" :: "r"(dst), "l"(src));
}
#define CP_COMMIT() asm volatile("cp.async.commit_group;" ::: "memory")
#define CP_WAIT1()  asm volatile("cp.async.wait_group 1;" ::: "memory")
#define CP_WAIT0()  asm volatile("cp.async.wait_group 0;" ::: "memory")

// ---------------- scoped atomics for the grid barrier ----------------
__device__ __forceinline__ unsigned ld_acquire(const unsigned* p) {
    unsigned v;
    asm volatile("ld.acquire.gpu.u32 %0, [%1];" : "=r"(v) : "l"(p) : "memory");
    return v;
}
__device__ __forceinline__ void st_release(unsigned* p, unsigned v) {
    asm volatile("st.release.gpu.u32 [%0], %1;" :: "l"(p), "r"(v) : "memory");
}

// ---------------- device scratch ----------------
__device__ float g_mu_h[H_DIM * H_DIM];    // fp32, [k][n] (bf16 at scan staging)
__device__ float g_d_h [H_DIM * H_DIM];
// xproj weights pre-merged in smem image: [8 ks][4 cg][4 tg][1024 n-slot] uint4
__device__ __align__(16) uint4 g_wx[8 * 16 * 1024];
__device__ __align__(16) __nv_bfloat16 g_xb16[S_LEN * B_DIM * I_DIM];  // bf16(x), k16-permuted
__device__ __align__(16) __nv_bfloat16 g_xq16[S_LEN * B_DIM * I_DIM];  // bf16(x*x), k16-permuted
// bf16 h transport, PAIR-PACKED layout: per row, per k-eighth ke, element for
// (chunk c=2p+s, frag-pos jp=4t+e) lives at ke*128 + p*32 + t*8 + s*4 + e.
__device__ __align__(16) __nv_bfloat16 g_hA[B_DIM * H_DIM];
__device__ __align__(16) __nv_bfloat16 g_hB[B_DIM * H_DIM];
// release flags: g_flags[bid*32], one 128B line per block, monotonic
__device__ __align__(128) unsigned g_flags[NB * 32];

// ---------------- prep ----------------
__global__ void prep_kernel(const float* __restrict__ m_in, const float* __restrict__ pi_in,
                            const float* __restrict__ chi_in,
                            const float* __restrict__ m_h, const float* __restrict__ pi_h,
                            const float* __restrict__ chi_h)
{
    int idx = blockIdx.x * blockDim.x + threadIdx.x;
    int stride = gridDim.x * blockDim.x;

    for (int i = idx; i < H_DIM * H_DIM; i += stride) {
        float m = m_h[i], pi = pi_h[i], chi = chi_h[i];
        float mu = (1.0f - pi) * m;
        float rho = (1.0f - pi) * (chi + m * m);
        g_mu_h[i] = mu;
        g_d_h[i]  = rho - mu * mu;
    }
    for (int i = idx; i < 8 * 16 * 1024; i += stride) {
        int n  = i & 1023;
        int tg = (i >> 10) & 3;
        int cgks = i >> 12;
        int kA = cgks * 16 + 2 * tg;
        int kB = kA + 8;

        float mv[4], dv[4];
        int kk[4] = {kA, kA + 1, kB, kB + 1};
#pragma unroll
        for (int j = 0; j < 4; j++) {
            int o = kk[j] * H_DIM + n;
            float m = m_in[o], pi = pi_in[o], chi = chi_in[o];
            float mu = (1.0f - pi) * m;
            mv[j] = mu;
            dv[j] = (1.0f - pi) * (chi + m * m) - mu * mu;
        }
        uint4 w;
        w.x = bpack(mv[0], mv[1]);
        w.y = bpack(mv[2], mv[3]);
        w.z = bpack(dv[0], dv[1]);
        w.w = bpack(dv[2], dv[3]);
        int nb = n >> 6, nl = n & 63;
        int slot = nb * 64 + ((nl + 2 * tg) & 63);
        g_wx[(i & ~1023) + slot] = w;
    }
    for (int i = idx; i < (B_DIM * H_DIM) / 2; i += stride)
        reinterpret_cast<uint32_t*>(g_hA)[i] = 0u;
    for (int i = idx; i < NB * 32; i += stride)
        g_flags[i] = 0u;
}

// ---------------- prep_x: bf16(x), bf16(x^2), k16-permuted ----------------
__global__ void prep_x_kernel(const float* __restrict__ x)
{
    int idx = blockIdx.x * blockDim.x + threadIdx.x;
    int stride = gridDim.x * blockDim.x;
    const int N = S_LEN * B_DIM * I_DIM;
    for (int i = idx; i < N; i += stride) {
        int k = i & (I_DIM - 1);
        int m = i >> 9;
        float v = x[i];
        int p = (k & ~15) | kperm16(k & 15);
        int o = (m << 9) | p;
        g_xb16[o] = __float2bfloat16(v);
        g_xq16[o] = __float2bfloat16(v * v);
    }
}

// ---------------- phase B: xproj via bf16 mma.m16n8k16, cp.async pipelined ----------------
#define XP_SMEM (98304)
#define BUF_SZ  49152

__global__ void __launch_bounds__(256, 2) xproj_kernel(const float* __restrict__ eps_in,
                                                       float* __restrict__ out)
{
    extern __shared__ char smx[];
    const uint32_t sb = smem_u32(smx);

    const int tid  = threadIdx.x;
    const int warp = tid >> 5, lane = tid & 31;
    const int gid = lane >> 2, tig = lane & 3;
    const int n_base = blockIdx.x * 64;
    const int m_base = blockIdx.y * 128;
    const int mg = (warp & 3) * 32;
    const int nh = (warp >> 2) * 32;

    auto issue = [&](int ks) {
        const uint32_t boff = sb + (ks & 1) * BUF_SZ;
        for (int i = tid; i < 1024; i += 256) {
            int r = i >> 3, u = i & 7;
            int up = u ^ ((r & 3) << 1);
            const char* src = (const char*)(g_xb16 + (size_t)(m_base + r) * I_DIM + ks * 64) + u * 16;
            const char* srq = (const char*)(g_xq16 + (size_t)(m_base + r) * I_DIM + ks * 64) + u * 16;
            cp16(boff + r * 128 + up * 16, src);
            cp16(boff + 16384 + r * 128 + up * 16, srq);
        }
        for (int i = tid; i < 1024; i += 256) {
            cp16(boff + 32768 + i * 16,
                 (const char*)(g_wx + (((ks * 16 + (i >> 6)) << 10) + n_base + (i & 63))));
        }
    };

    float cG[2][4][4] = {}, cD[2][4][4] = {};

    issue(0); CP_COMMIT();
    issue(1); CP_COMMIT();

    for (int ks = 0; ks < 8; ks++) {
        if (ks < 7) { CP_WAIT1(); } else { CP_WAIT0(); }
        __syncthreads();

        const char* xs = smx + (ks & 1) * BUF_SZ;
        const char* xq = xs + 16384;
        const uint4* w4 = (const uint4*)(xs + 32768);

#pragma unroll
        for (int c = 0; c < 4; c++) {
            uint2 ax[2][2], aq[2][2];
#pragma unroll
            for (int mt = 0; mt < 2; mt++) {
                int r0 = mg + mt * 16 + gid;
                int r1 = r0 + 8;
                int g0 = (c * 4 + tig) ^ ((r0 & 3) << 2);
                int g1 = (c * 4 + tig) ^ ((r1 & 3) << 2);
                ax[mt][0] = *(const uint2*)(xs + r0 * 128 + g0 * 8);
                ax[mt][1] = *(const uint2*)(xs + r1 * 128 + g1 * 8);
                aq[mt][0] = *(const uint2*)(xq + r0 * 128 + g0 * 8);
                aq[mt][1] = *(const uint2*)(xq + r1 * 128 + g1 * 8);
            }
#pragma unroll
            for (int nt = 0; nt < 4; nt++) {
                int nl = nh + nt * 8 + gid;
                uint4 w = w4[(c * 4 + tig) * 64 + ((nl + 2 * tig) & 63)];
#pragma unroll
                for (int mt = 0; mt < 2; mt++) {
                    mma16(cG[mt][nt], ax[mt][0].x, ax[mt][1].x, ax[mt][0].y, ax[mt][1].y, w.x, w.y);
                    mma16(cD[mt][nt], aq[mt][0].x, aq[mt][1].x, aq[mt][0].y, aq[mt][1].y, w.z, w.w);
                }
            }
        }
        __syncthreads();
        if (ks + 2 < 8) { issue(ks + 2); CP_COMMIT(); }
    }

#pragma unroll
    for (int mt = 0; mt < 2; mt++)
#pragma unroll
    for (int nt = 0; nt < 4; nt++) {
        int n = n_base + nh + nt * 8 + tig * 2;
#pragma unroll
        for (int half = 0; half < 2; half++) {
            int m = m_base + mg + mt * 16 + gid + half * 8;
            size_t off = (size_t)m * H_DIM + n;
            float2 e = *(const float2*)(eps_in + off);
            float2 o;
            o.x = cG[mt][nt][half * 2]     + e.x * sqrtf(cD[mt][nt][half * 2]     + EPS_C);
            o.y = cG[mt][nt][half * 2 + 1] + e.y * sqrtf(cD[mt][nt][half * 2 + 1] + EPS_C);
            *(float2*)(out + off) = o;
        }
    }
}

// ---------------- phase C: persistent scan via bf16 mma.m16n8k16 ----------------
// R13 sync structure (1 release flag/block, 8 polls/warp) + two memory-op
// reductions: (a) pair-packed h transport -> 8x LDG.128 per warp-step instead of
// 16x LDG.64; (b) nt=0 weight fragments hoisted into registers for all 512 steps
// -> 16x LDS.128 per warp-step instead of 32.
#define SC_SMEM (98304)

__global__ void __launch_bounds__(512, 1) scan_kernel(const float* __restrict__ eps_h,
                                                      float* __restrict__ out,
                                                      int write_last)
{
    extern __shared__ char smc[];
    uint4* wpk = (uint4*)smc;                // [64 cg][4 tig][16 n] uint4 = 64KB
    float* pG = (float*)(smc + 65536);       // [8 ke][32 b][16 n] = 16KB
    float* pD = pG + 4096;

    const int tid  = threadIdx.x;
    const int warp = tid >> 5, lane = tid & 31;
    const int gid = lane >> 2, tig = lane & 3;
    const int n_base = (blockIdx.x >> 1) * 16;
    const int b_base = (blockIdx.x & 1) * 32;
    const int half = blockIdx.x & 1;
    const int mt = warp & 1, ke = warp >> 1;
    const int bid = blockIdx.x;

    // this warp's producer flag (lanes 0..7 each own one)
    unsigned* my_flag = &g_flags[(((ke * 8 + lane) * 2) + half) * 32];

    // stage weights once: mu and d single bf16, packed {mu01, mu89, d01, d89}
    for (int i = tid; i < 4096; i += 512) {
        int cg = i >> 6, tg = (i >> 4) & 3, n = i & 15;
        int sidx = cg * 64 + tg * 16 + ((n + 2 * tg) & 15);
        int k0 = cg * 16 + 2 * tg;
        int gn = n_base + n;
        float m0 = g_mu_h[(size_t)k0 * H_DIM + gn];
        float m1 = g_mu_h[(size_t)(k0 + 1) * H_DIM + gn];
        float m8 = g_mu_h[(size_t)(k0 + 8) * H_DIM + gn];
        float m9 = g_mu_h[(size_t)(k0 + 9) * H_DIM + gn];
        float d0 = g_d_h[(size_t)k0 * H_DIM + gn];
        float d1 = g_d_h[(size_t)(k0 + 1) * H_DIM + gn];
        float d8 = g_d_h[(size_t)(k0 + 8) * H_DIM + gn];
        float d9 = g_d_h[(size_t)(k0 + 9) * H_DIM + gn];
        uint4 w;
        w.x = bpack(m0, m1);
        w.y = bpack(m8, m9);
        w.z = bpack(d0, d1);
        w.w = bpack(d8, d9);
        wpk[sidx] = w;
    }
    __syncthreads();

    // hoist nt=0 weight fragments (nl = gid) into registers for all steps
    uint4 wreg[8];
#pragma unroll
    for (int c = 0; c < 8; c++)
        wreg[c] = wpk[(ke * 8 + c) * 64 + tig * 16 + ((gid + 2 * tig) & 15)];

    const int r0 = b_base + mt * 16 + gid;
    const int eb = tid >> 4;                 // 0..31
    const int en = tid & 15;                 // 0..15
    const int gbrow = b_base + eb;
    const int ncol = n_base + en;
    // pair-packed h transport offset: block's 16 cols = one global chunk cg
    const int cgB = n_base >> 4;             // global 16-chunk of this block
    const int keB = cgB >> 3;                // k-eighth
    const int ccB = cgB & 7;                 // chunk within eighth
    const int ppB = ccB >> 1, ssB = ccB & 1;
    const int jp = kperm16(en);              // 4t + e
    const int hoff = gbrow * H_DIM + keB * 128 + ppB * 32 + (jp >> 2) * 8 + ssB * 4 + (jp & 3);

    // prefetch step-0 epilogue operands
    size_t toff = (size_t)gbrow * H_DIM + ncol;
    float epre = __ldg(eps_h + toff);
    float xpre = __ldcg(out + toff);
    __syncthreads();

    for (int t = 0; t < S_LEN; t++) {
        const __nv_bfloat16* hsrc = (t & 1) ? g_hB : g_hA;
        __nv_bfloat16* hdst = (t & 1) ? g_hA : g_hB;

        // ---- per-warp producer gate (skip t=0: h0 preset by prep) ----
        if (t > 0) {
            if (lane < 8) {
                const unsigned tgt = (unsigned)t;
                while (ld_acquire(my_flag) < tgt) { }
            }
            __syncwarp();
        }

        // ---- preload h fragments: 8 independent LDG.128 (pair-packed) ----
        const __nv_bfloat16* hr0 = hsrc + (size_t)r0 * H_DIM + ke * 128 + tig * 8;
        const __nv_bfloat16* hr1 = hr0 + 8 * H_DIM;
        uint4 u0[4], u1[4];
#pragma unroll
        for (int p = 0; p < 4; p++) {
            u0[p] = __ldcg((const uint4*)(hr0 + p * 32));
            u1[p] = __ldcg((const uint4*)(hr1 + p * 32));
        }

        float cG[2][4] = {}, cD[2][4] = {};
#pragma unroll
        for (int p = 0; p < 4; p++) {
#pragma unroll
            for (int s = 0; s < 2; s++) {
                const int c = 2 * p + s;
                const int cg = ke * 8 + c;
                uint32_t a0 = s ? u0[p].z : u0[p].x;
                uint32_t a2 = s ? u0[p].w : u0[p].y;
                uint32_t a1 = s ? u1[p].z : u1[p].x;
                uint32_t a3 = s ? u1[p].w : u1[p].y;
                uint32_t q0 = mulbf2(a0, a0), q2 = mulbf2(a2, a2);
                uint32_t q1 = mulbf2(a1, a1), q3 = mulbf2(a3, a3);
                // nt = 0: register-resident weights
                uint4 w0 = wreg[c];
                mma16(cG[0], a0, a1, a2, a3, w0.x, w0.y);
                mma16(cD[0], q0, q1, q2, q3, w0.z, w0.w);
                // nt = 1: smem weights
                uint4 w1 = wpk[cg * 64 + tig * 16 + ((8 + gid + 2 * tig) & 15)];
                mma16(cG[1], a0, a1, a2, a3, w1.x, w1.y);
                mma16(cD[1], q0, q1, q2, q3, w1.z, w1.w);
            }
        }

        // partials -> smem
        const int rowa = ke * 32 + mt * 16 + gid;
#pragma unroll
        for (int nt = 0; nt < 2; nt++) {
            int colb = nt * 8 + tig * 2;
            *(float2*)&pG[rowa * 16 + colb]       = make_float2(cG[nt][0], cG[nt][1]);
            *(float2*)&pG[(rowa + 8) * 16 + colb] = make_float2(cG[nt][2], cG[nt][3]);
            *(float2*)&pD[rowa * 16 + colb]       = make_float2(cD[nt][0], cD[nt][1]);
            *(float2*)&pD[(rowa + 8) * 16 + colb] = make_float2(cD[nt][2], cD[nt][3]);
        }
        __syncthreads();

        // reduce 8 k-slices + epilogue (1 output per thread)
        float G = 0.0f, D = 0.0f;
#pragma unroll
        for (int q = 0; q < 8; q++) {
            G += pG[(q * 32 + eb) * 16 + en];
            D += pD[(q * 32 + eb) * 16 + en];
        }
        float h = tanh_ap(G + epre * sqrtf(D + EPS_C) + xpre);
        hdst[hoff] = __float2bfloat16(h);    // h transport: the only critical store

        if (t == S_LEN - 1) {
            out[toff] = h;
            if (write_last)
                out[(size_t)S_LEN * B_DIM * H_DIM + gbrow * H_DIM + ncol] = h;
            break;
        }

        // ---- release: all block h stores done -> publish flag ----
        __syncthreads();                      // h stores + psum reads complete
        if (tid == 0)
            st_release(&g_flags[bid * 32], (unsigned)(t + 1));
        // hidden work: current out-store + next-step operand prefetch
        out[toff] = h;
        toff = (size_t)((t + 1) * B_DIM + gbrow) * H_DIM + ncol;
        epre = __ldg(eps_h + toff);
        xpre = __ldcg(out + toff);
    }
}

// ---------------- launch ----------------
extern "C" void kernel_launch(void* const* d_in, const int* in_sizes, int n_in,
                              void* d_out, int out_size)
{
    (void)in_sizes; (void)n_in;
    const float* x      = (const float*)d_in[0];
    const float* eps_in = (const float*)d_in[1];
    const float* eps_h  = (const float*)d_in[2];
    const float* m_in   = (const float*)d_in[3];
    const float* pi_in  = (const float*)d_in[4];
    const float* chi_in = (const float*)d_in[5];
    const float* m_h    = (const float*)d_in[6];
    const float* pi_h   = (const float*)d_in[7];
    const float* chi_h  = (const float*)d_in[8];
    float* out = (float*)d_out;

    prep_kernel<<<1024, 256>>>(m_in, pi_in, chi_in, m_h, pi_h, chi_h);
    prep_x_kernel<<<8192, 256>>>(x);

    cudaFuncSetAttribute(xproj_kernel, cudaFuncAttributeMaxDynamicSharedMemorySize, XP_SMEM);
    dim3 gB(H_DIM / 64, (S_LEN * B_DIM) / 128);
    xproj_kernel<<<gB, 256, XP_SMEM>>>(eps_in, out);

    cudaFuncSetAttribute(scan_kernel, cudaFuncAttributeMaxDynamicSharedMemorySize, SC_SMEM);
    int write_last = (out_size >= S_LEN * B_DIM * H_DIM + B_DIM * H_DIM) ? 1 : 0;
    scan_kernel<<<NB, 512, SC_SMEM>>>(eps_h, out, write_last);
}